// round 7
// baseline (speedup 1.0000x reference)
#include <cuda_runtime.h>
#include <cuda_bf16.h>
#include <math.h>
#include <stdint.h>

#define DT_STEP 0.1f
#define EPS_TAU 1e-6f

constexpr int B = 256, T = 512, I = 64, H = 512, O = 64;
constexpr int GRID = 144;  // 128 layer CTAs + 16 out-proj CTAs; all co-resident
constexpr int KP = H / 2;  // 256 kpairs per row

// smem (b32 units): weight fragments + misc
constexpr int WA_HI = 0;          // 9216 pairs (K=576)
constexpr int WA_LO = 9216;
constexpr int WB_HI = 18432;      // 16384 pairs (K=1024)
constexpr int WB_LO = 34816;
constexpr int MISC = 51200;       // 128 floats
constexpr int SMEM_BYTES = (MISC + 128) * 4;  // ~205.3 KB

// Packed hidden-state fragments: [buf][row*KP + kpair] = uint2(hi_bf16x2, lo_bf16x2)
__device__ uint2 g_ph0[2][B * KP];
__device__ uint2 g_ph1[2][B * KP];
__device__ uint2 g_px[B * T * (I / 2)];  // x pre-split, same (hi,lo) packing
__device__ unsigned g_arrive;
__device__ volatile unsigned g_release;

__global__ void k_init() {
    int idx = blockIdx.x * blockDim.x + threadIdx.x;
    if (idx < B * KP) {
        g_ph0[0][idx] = make_uint2(0u, 0u);
        g_ph0[1][idx] = make_uint2(0u, 0u);
        g_ph1[0][idx] = make_uint2(0u, 0u);
        g_ph1[1][idx] = make_uint2(0u, 0u);
    }
    if (idx == 0) { g_arrive = 0; g_release = 0; }
}

__device__ __forceinline__ uint32_t pack2(float e0, float e1) {
    uint32_t r;  // low half = e0
    asm("cvt.rn.bf16x2.f32 %0, %1, %2;" : "=r"(r) : "f"(e1), "f"(e0));
    return r;
}
__device__ __forceinline__ float bfr(float x) {
    return __bfloat162float(__float2bfloat16_rn(x));
}
__device__ __forceinline__ uint2 packpair(float e0, float e1) {
    float h0 = bfr(e0), h1 = bfr(e1);
    return make_uint2(pack2(h0, h1), pack2(e0 - h0, e1 - h1));
}

// One-time x conversion: fp32 pairs -> (hi,lo) bf16x2 pairs (layout-identical).
__global__ void k_prep(const float* __restrict__ x) {
    int n = B * T * (I / 2);
    for (int j = blockIdx.x * blockDim.x + threadIdx.x; j < n;
         j += gridDim.x * blockDim.x) {
        float2 v = reinterpret_cast<const float2*>(x)[j];
        g_px[j] = packpair(v.x, v.y);
    }
}

// m16n8k16 row.col f32.bf16.bf16.f32
__device__ __forceinline__ void mmaw(float* d, uint4 a, uint2 b) {
    asm volatile(
        "mma.sync.aligned.m16n8k16.row.col.f32.bf16.bf16.f32 "
        "{%0,%1,%2,%3},{%4,%5,%6,%7},{%8,%9},{%0,%1,%2,%3};"
        : "+f"(d[0]), "+f"(d[1]), "+f"(d[2]), "+f"(d[3])
        : "r"(a.x), "r"(a.y), "r"(a.z), "r"(a.w), "r"(b.x), "r"(b.y));
}

// Grid barrier; __threadfence() orders epilogue stores and invalidates L1D.
__device__ __forceinline__ void gsync(unsigned& epoch) {
    epoch++;
    __syncthreads();
    __threadfence();
    if (threadIdx.x == 0) {
        unsigned ticket = atomicAdd(&g_arrive, 1u) + 1u;
        if (ticket == (unsigned)GRID * epoch) g_release = epoch;
        else while (g_release < epoch) {}
    }
    __syncthreads();
    __threadfence();
}

// One-time weight staging into fragment order (same layout as round 6).
__device__ void stage_wfrag(uint32_t* sm32, int hiOff, int loOff, int pairs,
                            const float* W0, int s0, int klim,
                            const float* W1, int s1) {
    for (int idx = threadIdx.x; idx < pairs; idx += 256) {
        int s = idx & 1, lane = (idx >> 1) & 31;
        int nb = (idx >> 6) & 3, ktG = idx >> 8;
        int gid = lane >> 2, tig = lane & 3;
        int n = nb * 8 + gid, k = ktG * 16 + tig * 2 + s * 8;
        const float* src; int kk;
        if (k < klim) { src = W0 + n * s0; kk = k; }
        else { src = W1 + n * s1; kk = k - klim; }
        float w0 = src[kk], w1 = src[kk + 1];
        float h0 = bfr(w0), h1 = bfr(w1);
        sm32[hiOff + idx] = pack2(h0, h1);
        sm32[loOff + idx] = pack2(w0 - h0, w1 - h1);
    }
}

// 3-MMA (hi*hi, hi*lo, lo*hi) accumulation for one k16-tile; A-frags straight
// from packed global (4x LDG.64), B-frags from resident smem (2x LDS.64).
__device__ __forceinline__ void mma_k(float* acc, const uint2* __restrict__ pA,
                                      int rstride, int g, int kp0,
                                      const uint32_t* whi, const uint32_t* wlo,
                                      int widx, int lane) {
    uint2 u0 = pA[g * rstride + kp0];
    uint2 u1 = pA[(g + 8) * rstride + kp0];
    uint2 u2 = pA[g * rstride + kp0 + 4];
    uint2 u3 = pA[(g + 8) * rstride + kp0 + 4];
    uint2 bh = *(const uint2*)(whi + (widx * 32 + lane) * 2);
    uint2 bl = *(const uint2*)(wlo + (widx * 32 + lane) * 2);
    uint4 ah = make_uint4(u0.x, u1.x, u2.x, u3.x);
    uint4 al = make_uint4(u0.y, u1.y, u2.y, u3.y);
    mmaw(acc, ah, bh);
    mmaw(acc, ah, bl);
    mmaw(acc, al, bh);
}

__global__ __launch_bounds__(256, 1) void k_scan(
    const float* __restrict__ x, const float* __restrict__ Win0,
    const float* __restrict__ bin0, const float* __restrict__ A0,
    const float* __restrict__ tau0, const float* __restrict__ Win1,
    const float* __restrict__ bin1, const float* __restrict__ A1,
    const float* __restrict__ tau1, const float* __restrict__ Wout,
    const float* __restrict__ bout, float* __restrict__ out) {
    extern __shared__ uint32_t sm[];
    float* miscf = (float*)(sm + MISC);
    const int tid = threadIdx.x, bx = blockIdx.x;
    const int w = tid >> 5, lane = tid & 31;
    const int gid = lane >> 2, tig = lane & 3;
    const int rb = w & 1, nb = w >> 1;
    const bool is_main = (bx < 128);
    int row0, col0;
    if (is_main) { row0 = (bx >> 4) * 32; col0 = (bx & 15) * 32; }
    else { int idx = bx - 128; row0 = (idx >> 1) * 32; col0 = (idx & 1) * 32; }

    if (is_main) {
        stage_wfrag(sm, WA_HI, WA_LO, 9216, A0 + col0 * H, H, 512,
                    Win0 + col0 * I, I);
        stage_wfrag(sm, WB_HI, WB_LO, 16384, Win1 + col0 * H, H, 512,
                    A1 + col0 * H, H);
        if (tid < 32) {
            miscf[tid] = bin0[col0 + tid];
            miscf[32 + tid] = 1.0f / (fabsf(tau0[col0 + tid]) + EPS_TAU);
            miscf[64 + tid] = bin1[col0 + tid];
            miscf[96 + tid] = 1.0f / (fabsf(tau1[col0 + tid]) + EPS_TAU);
        }
    } else {
        stage_wfrag(sm, 0, 8192, 8192, Wout + col0 * H, H, 1 << 20, Wout, H);
        if (tid < 32) miscf[tid] = bout[col0 + tid];
    }
    __syncthreads();

    const int g = row0 + rb * 16 + gid;      // absolute D-frag rows g, g+8
    const int gc = col0 + nb * 8 + tig * 2;  // D-frag cols gc, gc+1
    const int ci = nb * 8 + tig * 2;
    const int kpw = gc >> 1;                 // kpair this thread writes
    // hidden state lives in registers (this CTA owns its tile exclusively)
    float hp0[4] = {0.f, 0.f, 0.f, 0.f};
    float hp1[4] = {0.f, 0.f, 0.f, 0.f};
    unsigned epoch = 0;

    for (int t = 0; t < T; t++) {
        const int pr = t & 1, pw = pr ^ 1;

        // ---------------- phase A ----------------
        if (is_main) {
            float acc[4] = {0.f, 0.f, 0.f, 0.f};
            const uint2* pA = g_ph0[pr];
#pragma unroll 4
            for (int ktG = 0; ktG < 32; ktG++)
                mma_k(acc, pA, KP, g, ktG * 8 + tig, sm + WA_HI, sm + WA_LO,
                      ktG * 4 + nb, lane);
            const uint2* pX = g_px + t * (I / 2);
#pragma unroll
            for (int kt = 0; kt < 4; kt++)
                mma_k(acc, pX, T * (I / 2), g, kt * 8 + tig, sm + WA_HI,
                      sm + WA_LO, (32 + kt) * 4 + nb, lane);
            float b0v = miscf[ci], b1v = miscf[ci + 1];
            float i0 = miscf[32 + ci], i1 = miscf[32 + ci + 1];
            hp0[0] += DT_STEP * i0 * (tanhf(acc[0] + b0v) - hp0[0]);
            hp0[1] += DT_STEP * i1 * (tanhf(acc[1] + b1v) - hp0[1]);
            hp0[2] += DT_STEP * i0 * (tanhf(acc[2] + b0v) - hp0[2]);
            hp0[3] += DT_STEP * i1 * (tanhf(acc[3] + b1v) - hp0[3]);
            g_ph0[pw][g * KP + kpw] = packpair(hp0[0], hp0[1]);
            g_ph0[pw][(g + 8) * KP + kpw] = packpair(hp0[2], hp0[3]);
        } else if (t > 0) {
            float acc[4] = {0.f, 0.f, 0.f, 0.f};
            const uint2* pA = g_ph1[pr];
#pragma unroll 4
            for (int ktG = 0; ktG < 32; ktG++)
                mma_k(acc, pA, KP, g, ktG * 8 + tig, sm + 0, sm + 8192,
                      ktG * 4 + nb, lane);
            float b0v = miscf[ci], b1v = miscf[ci + 1];
            *(float2*)(out + g * (T * O) + (t - 1) * O + gc) =
                make_float2(acc[0] + b0v, acc[1] + b1v);
            *(float2*)(out + (g + 8) * (T * O) + (t - 1) * O + gc) =
                make_float2(acc[2] + b0v, acc[3] + b1v);
        }
        gsync(epoch);

        // ---------------- phase B ----------------
        if (is_main) {
            float acc[4] = {0.f, 0.f, 0.f, 0.f};
            const uint2* pD = g_ph0[pw];  // h0' written in phase A
            const uint2* pR = g_ph1[pr];
#pragma unroll 4
            for (int ktG = 0; ktG < 32; ktG++)
                mma_k(acc, pD, KP, g, ktG * 8 + tig, sm + WB_HI, sm + WB_LO,
                      ktG * 4 + nb, lane);
#pragma unroll 4
            for (int ktG = 32; ktG < 64; ktG++)
                mma_k(acc, pR, KP, g, (ktG - 32) * 8 + tig, sm + WB_HI,
                      sm + WB_LO, ktG * 4 + nb, lane);
            float b0v = miscf[64 + ci], b1v = miscf[64 + ci + 1];
            float i0 = miscf[96 + ci], i1 = miscf[96 + ci + 1];
            hp1[0] += DT_STEP * i0 * (tanhf(acc[0] + b0v) - hp1[0]);
            hp1[1] += DT_STEP * i1 * (tanhf(acc[1] + b1v) - hp1[1]);
            hp1[2] += DT_STEP * i0 * (tanhf(acc[2] + b0v) - hp1[2]);
            hp1[3] += DT_STEP * i1 * (tanhf(acc[3] + b1v) - hp1[3]);
            g_ph1[pw][g * KP + kpw] = packpair(hp1[0], hp1[1]);
            g_ph1[pw][(g + 8) * KP + kpw] = packpair(hp1[2], hp1[3]);
        }
        gsync(epoch);
    }

    // ---- epilogue: y(T-1); final h1 lives in buf 0 ----
    if (!is_main) {
        float acc[4] = {0.f, 0.f, 0.f, 0.f};
        const uint2* pA = g_ph1[0];
#pragma unroll 4
        for (int ktG = 0; ktG < 32; ktG++)
            mma_k(acc, pA, KP, g, ktG * 8 + tig, sm + 0, sm + 8192,
                  ktG * 4 + nb, lane);
        float b0v = miscf[ci], b1v = miscf[ci + 1];
        *(float2*)(out + g * (T * O) + (T - 1) * O + gc) =
            make_float2(acc[0] + b0v, acc[1] + b1v);
        *(float2*)(out + (g + 8) * (T * O) + (T - 1) * O + gc) =
            make_float2(acc[2] + b0v, acc[3] + b1v);
    }
}

extern "C" void kernel_launch(void* const* d_in, const int* in_sizes, int n_in,
                              void* d_out, int out_size) {
    const float* x    = (const float*)d_in[0];
    const float* Win0 = (const float*)d_in[1];
    const float* bin0 = (const float*)d_in[2];
    const float* A0   = (const float*)d_in[3];
    const float* tau0 = (const float*)d_in[4];
    const float* Win1 = (const float*)d_in[5];
    const float* bin1 = (const float*)d_in[6];
    const float* A1   = (const float*)d_in[7];
    const float* tau1 = (const float*)d_in[8];
    const float* Wout = (const float*)d_in[9];
    const float* bout = (const float*)d_in[10];
    float* out = (float*)d_out;

    cudaFuncSetAttribute(k_scan, cudaFuncAttributeMaxDynamicSharedMemorySize,
                         SMEM_BYTES);

    k_init<<<(B * KP + 255) / 256, 256>>>();
    k_prep<<<256, 256>>>(x);
    k_scan<<<GRID, 256, SMEM_BYTES>>>(x, Win0, bin0, A0, tau0, Win1, bin1, A1,
                                      tau1, Wout, bout, out);
}

// round 8
// speedup vs baseline: 1.5316x; 1.5316x over previous
#include <cuda_runtime.h>
#include <cuda_bf16.h>
#include <math.h>
#include <stdint.h>

#define DT_STEP 0.1f
#define EPS_TAU 1e-6f

constexpr int B = 256, T = 512, I = 64, H = 512, O = 64;
constexpr int GRID = 144;   // 128 layer CTAs + 16 out-proj CTAs; all co-resident
constexpr int KP = H / 2;   // 256 kpairs per h row
constexpr int NKT = KP / 8; // 32 k16-tiles per h row

// smem b32 offsets (weight frags resident, fragment order; + act chunk bufs)
constexpr int WA_HI = 0;        // 9216 (K=576: 36 ktiles * 4 nb * 32 lanes * 2)
constexpr int WA_LO = 9216;
constexpr int WB_HI = 18432;    // 16384 (K=1024)
constexpr int WB_LO = 34816;
constexpr int ACT = 51200;      // 2 bufs x (1024 hi + 1024 lo)
constexpr int MISC = ACT + 4096;
constexpr int SMEM_BYTES = (MISC + 128) * 4;  // 221,696 B (fits; same as R6)

// Global activation planes in MMA FRAGMENT ORDER:
// plane idx for (row r, kpair kp): rbg=r>>4, gid=r&7, rowhalf=(r>>3)&1,
// kt=kp>>3, lane=gid*4+(kp&3), j=rowhalf+2*((kp>>2)&1)
// idx = ((rbg*NKT+kt)*32+lane)*4+j   -> chunks are contiguous 512-u32 runs.
constexpr int HPLANE = (B / 16) * NKT * 128;    // 65536 u32
constexpr int XPLANE = (B / 16) * T * 4 * 128;  // 4,194,304 u32

__device__ uint32_t g_h0hi[2][HPLANE], g_h0lo[2][HPLANE];
__device__ uint32_t g_h1hi[2][HPLANE], g_h1lo[2][HPLANE];
__device__ uint32_t g_pxhi[XPLANE], g_pxlo[XPLANE];
__device__ unsigned g_arrive;
__device__ volatile unsigned g_release;

__global__ void k_init() {
    int idx = blockIdx.x * blockDim.x + threadIdx.x;
    if (idx < HPLANE) {
        g_h0hi[0][idx] = 0u; g_h0hi[1][idx] = 0u;
        g_h0lo[0][idx] = 0u; g_h0lo[1][idx] = 0u;
        g_h1hi[0][idx] = 0u; g_h1hi[1][idx] = 0u;
        g_h1lo[0][idx] = 0u; g_h1lo[1][idx] = 0u;
    }
    if (idx == 0) { g_arrive = 0; g_release = 0; }
}

__device__ __forceinline__ uint32_t pack2(float e0, float e1) {
    uint32_t r;  // low half = e0
    asm("cvt.rn.bf16x2.f32 %0, %1, %2;" : "=r"(r) : "f"(e1), "f"(e0));
    return r;
}
__device__ __forceinline__ float bfr(float x) {
    return __bfloat162float(__float2bfloat16_rn(x));
}
__device__ __forceinline__ uint2 packpair(float e0, float e1) {
    float h0 = bfr(e0), h1 = bfr(e1);
    return make_uint2(pack2(h0, h1), pack2(e0 - h0, e1 - h1));
}

// Pre-pack x into fragment-order planes. i enumerates (rbg,t,ktx,lane).
__global__ void k_prep(const float* __restrict__ x) {
    int n = (B / 16) * T * 4 * 32;
    for (int i = blockIdx.x * blockDim.x + threadIdx.x; i < n;
         i += gridDim.x * blockDim.x) {
        int lane = i & 31, ktx = (i >> 5) & 3, t = (i >> 7) & (T - 1), rbg = i >> 16;
        int gid = lane >> 2, tigf = lane & 3;
        int kp0 = ktx * 8 + tigf;
        const float* xb = x + (size_t)(rbg * 16 + gid) * (T * I) + t * I;
        const float* xb8 = xb + 8 * (T * I);
        float2 v0 = *(const float2*)(xb + kp0 * 2);
        float2 v1 = *(const float2*)(xb8 + kp0 * 2);
        float2 v2 = *(const float2*)(xb + (kp0 + 4) * 2);
        float2 v3 = *(const float2*)(xb8 + (kp0 + 4) * 2);
        uint2 p0 = packpair(v0.x, v0.y), p1 = packpair(v1.x, v1.y);
        uint2 p2 = packpair(v2.x, v2.y), p3 = packpair(v3.x, v3.y);
        *(uint4*)(g_pxhi + i * 4) = make_uint4(p0.x, p1.x, p2.x, p3.x);
        *(uint4*)(g_pxlo + i * 4) = make_uint4(p0.y, p1.y, p2.y, p3.y);
    }
}

__device__ __forceinline__ void mmaw(float* d, uint4 a, uint2 b) {
    asm volatile(
        "mma.sync.aligned.m16n8k16.row.col.f32.bf16.bf16.f32 "
        "{%0,%1,%2,%3},{%4,%5,%6,%7},{%8,%9},{%0,%1,%2,%3};"
        : "+f"(d[0]), "+f"(d[1]), "+f"(d[2]), "+f"(d[3])
        : "r"(a.x), "r"(a.y), "r"(a.z), "r"(a.w), "r"(b.x), "r"(b.y));
}

__device__ __forceinline__ void gsync(unsigned& epoch) {
    epoch++;
    __syncthreads();
    __threadfence();
    if (threadIdx.x == 0) {
        unsigned ticket = atomicAdd(&g_arrive, 1u) + 1u;
        if (ticket == (unsigned)GRID * epoch) g_release = epoch;
        else while (g_release < epoch) {}
    }
    __syncthreads();
    __threadfence();
}

// One-time weight staging into fragment order (unchanged from round 6).
__device__ void stage_wfrag(uint32_t* sm32, int hiOff, int loOff, int pairs,
                            const float* W0, int s0, int klim,
                            const float* W1, int s1) {
    for (int idx = threadIdx.x; idx < pairs; idx += 256) {
        int s = idx & 1, lane = (idx >> 1) & 31;
        int nb = (idx >> 6) & 3, ktG = idx >> 8;
        int gid = lane >> 2, tig = lane & 3;
        int n = nb * 8 + gid, k = ktG * 16 + tig * 2 + s * 8;
        const float* src; int kk;
        if (k < klim) { src = W0 + n * s0; kk = k; }
        else { src = W1 + n * s1; kk = k - klim; }
        float w0 = src[kk], w1 = src[kk + 1];
        float h0 = bfr(w0), h1 = bfr(w1);
        sm32[hiOff + idx] = pack2(h0, h1);
        sm32[loOff + idx] = pack2(w0 - h0, w1 - h1);
    }
}

// Pure-copy chunk staging: 1 LDG.128 + 1 STS.128 per plane per thread.
__device__ __forceinline__ void stage_ld(uint4& vh, uint4& vl,
                                         const uint32_t* hp, const uint32_t* lp,
                                         int off0, int off1) {
    int tid = threadIdx.x;
    int off = ((tid >> 7) ? off1 : off0) + (tid & 127) * 4;
    vh = *(const uint4*)(hp + off);
    vl = *(const uint4*)(lp + off);
}
__device__ __forceinline__ void stage_st(uint32_t* sm, int bufIdx,
                                         uint4 vh, uint4 vl) {
    int tid = threadIdx.x;
    uint32_t* d = sm + ACT + bufIdx * 2048 + (tid >> 7) * 512 + (tid & 127) * 4;
    *(uint4*)d = vh;
    *(uint4*)(d + 1024) = vl;
}

// 4 k16-tiles of one staged chunk: A hi/lo from smem (2 LDS.128), B from
// resident weight frags (2 LDS.64), 3 HMMA each.
__device__ __forceinline__ void mma_chunk(float* acc, const uint32_t* smact,
                                          const uint32_t* whi, const uint32_t* wlo,
                                          int ktG0, int rb, int nb, int lane) {
#pragma unroll
    for (int ktl = 0; ktl < 4; ktl++) {
        const uint32_t* a = smact + (rb * 4 + ktl) * 128 + lane * 4;
        uint4 ah = *(const uint4*)a;
        uint4 al = *(const uint4*)(a + 1024);
        int widx = (ktG0 + ktl) * 4 + nb;
        uint2 bh = *(const uint2*)(whi + (widx * 32 + lane) * 2);
        uint2 bl = *(const uint2*)(wlo + (widx * 32 + lane) * 2);
        mmaw(acc, ah, bh);
        mmaw(acc, ah, bl);
        mmaw(acc, al, bh);
    }
}

__global__ __launch_bounds__(256, 1) void k_scan(
    const float* __restrict__ x, const float* __restrict__ Win0,
    const float* __restrict__ bin0, const float* __restrict__ A0,
    const float* __restrict__ tau0, const float* __restrict__ Win1,
    const float* __restrict__ bin1, const float* __restrict__ A1,
    const float* __restrict__ tau1, const float* __restrict__ Wout,
    const float* __restrict__ bout, float* __restrict__ out) {
    extern __shared__ uint32_t sm[];
    float* miscf = (float*)(sm + MISC);
    const int tid = threadIdx.x, bx = blockIdx.x;
    const int w = tid >> 5, lane = tid & 31;
    const int gid = lane >> 2, tig = lane & 3;
    const int rb = w & 1, nb = w >> 1;
    const bool is_main = (bx < 128);
    int row0, col0;
    if (is_main) { row0 = (bx >> 4) * 32; col0 = (bx & 15) * 32; }
    else { int idx = bx - 128; row0 = (idx >> 1) * 32; col0 = (idx & 1) * 32; }

    if (is_main) {
        stage_wfrag(sm, WA_HI, WA_LO, 9216, A0 + col0 * H, H, 512,
                    Win0 + col0 * I, I);
        stage_wfrag(sm, WB_HI, WB_LO, 16384, Win1 + col0 * H, H, 512,
                    A1 + col0 * H, H);
        if (tid < 32) {
            miscf[tid] = bin0[col0 + tid];
            miscf[32 + tid] = 1.0f / (fabsf(tau0[col0 + tid]) + EPS_TAU);
            miscf[64 + tid] = bin1[col0 + tid];
            miscf[96 + tid] = 1.0f / (fabsf(tau1[col0 + tid]) + EPS_TAU);
        }
    } else {
        stage_wfrag(sm, 0, 8192, 8192, Wout + col0 * H, H, 1 << 20, Wout, H);
        if (tid < 32) miscf[tid] = bout[col0 + tid];
    }
    __syncthreads();

    const int g = row0 + rb * 16 + gid;
    const int gc = col0 + nb * 8 + tig * 2;
    const int ci = nb * 8 + tig * 2;
    const int kpw = gc >> 1;
    const int rbg0 = row0 >> 4;
    // packed-h write index (rows g, g+8 -> consecutive j slots, one STG.64/plane)
    const int wrbg = rbg0 + rb;
    const int widxh = ((wrbg * NKT + (kpw >> 3)) * 32 + gid * 4 + (kpw & 3)) * 4 +
                      ((kpw >> 2) & 1) * 2;
    const int oh0 = rbg0 * NKT * 128, oh1 = (rbg0 + 1) * NKT * 128;

    float hp0[4] = {0.f, 0.f, 0.f, 0.f};
    float hp1[4] = {0.f, 0.f, 0.f, 0.f};
    unsigned epoch = 0;

    for (int t = 0; t < T; t++) {
        const int pr = t & 1, pw = pr ^ 1;

        // ---------------- phase A ----------------
        if (is_main) {
            const uint32_t* hp = g_h0hi[pr];
            const uint32_t* lp = g_h0lo[pr];
            const int ox0 = (rbg0 * T + t) * 512, ox1 = ((rbg0 + 1) * T + t) * 512;
            float acc[4] = {0.f, 0.f, 0.f, 0.f};
            uint4 vh, vl;
            stage_ld(vh, vl, hp, lp, oh0, oh1);
            stage_st(sm, 0, vh, vl);
#pragma unroll 1
            for (int c = 0; c < 9; c++) {
                __syncthreads();
                if (c < 8) {
                    if (c < 7) stage_ld(vh, vl, hp, lp, oh0 + (c + 1) * 512,
                                        oh1 + (c + 1) * 512);
                    else stage_ld(vh, vl, g_pxhi, g_pxlo, ox0, ox1);
                }
                mma_chunk(acc, sm + ACT + (c & 1) * 2048, sm + WA_HI, sm + WA_LO,
                          c * 4, rb, nb, lane);
                if (c < 8) stage_st(sm, (c + 1) & 1, vh, vl);
            }
            float b0v = miscf[ci], b1v = miscf[ci + 1];
            float i0 = miscf[32 + ci], i1 = miscf[32 + ci + 1];
            hp0[0] += DT_STEP * i0 * (tanhf(acc[0] + b0v) - hp0[0]);
            hp0[1] += DT_STEP * i1 * (tanhf(acc[1] + b1v) - hp0[1]);
            hp0[2] += DT_STEP * i0 * (tanhf(acc[2] + b0v) - hp0[2]);
            hp0[3] += DT_STEP * i1 * (tanhf(acc[3] + b1v) - hp0[3]);
            uint2 u0 = packpair(hp0[0], hp0[1]);
            uint2 u1 = packpair(hp0[2], hp0[3]);
            *(uint2*)(g_h0hi[pw] + widxh) = make_uint2(u0.x, u1.x);
            *(uint2*)(g_h0lo[pw] + widxh) = make_uint2(u0.y, u1.y);
        } else if (t > 0) {
            const uint32_t* hp = g_h1hi[pr];
            const uint32_t* lp = g_h1lo[pr];
            float acc[4] = {0.f, 0.f, 0.f, 0.f};
            uint4 vh, vl;
            stage_ld(vh, vl, hp, lp, oh0, oh1);
            stage_st(sm, 0, vh, vl);
#pragma unroll 1
            for (int c = 0; c < 8; c++) {
                __syncthreads();
                if (c < 7) stage_ld(vh, vl, hp, lp, oh0 + (c + 1) * 512,
                                    oh1 + (c + 1) * 512);
                mma_chunk(acc, sm + ACT + (c & 1) * 2048, sm + 0, sm + 8192,
                          c * 4, rb, nb, lane);
                if (c < 7) stage_st(sm, (c + 1) & 1, vh, vl);
            }
            float b0v = miscf[ci], b1v = miscf[ci + 1];
            *(float2*)(out + g * (T * O) + (t - 1) * O + gc) =
                make_float2(acc[0] + b0v, acc[1] + b1v);
            *(float2*)(out + (g + 8) * (T * O) + (t - 1) * O + gc) =
                make_float2(acc[2] + b0v, acc[3] + b1v);
        }
        gsync(epoch);

        // ---------------- phase B ----------------
        if (is_main) {
            const uint32_t* dh = g_h0hi[pw];  // h0' from phase A
            const uint32_t* dl = g_h0lo[pw];
            const uint32_t* rh = g_h1hi[pr];
            const uint32_t* rl = g_h1lo[pr];
            float acc[4] = {0.f, 0.f, 0.f, 0.f};
            uint4 vh, vl;
            stage_ld(vh, vl, dh, dl, oh0, oh1);
            stage_st(sm, 0, vh, vl);
#pragma unroll 1
            for (int c = 0; c < 16; c++) {
                __syncthreads();
                if (c < 15) {
                    int cn = c + 1;
                    if (cn < 8) stage_ld(vh, vl, dh, dl, oh0 + cn * 512,
                                         oh1 + cn * 512);
                    else stage_ld(vh, vl, rh, rl, oh0 + (cn - 8) * 512,
                                  oh1 + (cn - 8) * 512);
                }
                mma_chunk(acc, sm + ACT + (c & 1) * 2048, sm + WB_HI, sm + WB_LO,
                          c * 4, rb, nb, lane);
                if (c < 15) stage_st(sm, (c + 1) & 1, vh, vl);
            }
            float b0v = miscf[64 + ci], b1v = miscf[64 + ci + 1];
            float i0 = miscf[96 + ci], i1 = miscf[96 + ci + 1];
            hp1[0] += DT_STEP * i0 * (tanhf(acc[0] + b0v) - hp1[0]);
            hp1[1] += DT_STEP * i1 * (tanhf(acc[1] + b1v) - hp1[1]);
            hp1[2] += DT_STEP * i0 * (tanhf(acc[2] + b0v) - hp1[2]);
            hp1[3] += DT_STEP * i1 * (tanhf(acc[3] + b1v) - hp1[3]);
            uint2 u0 = packpair(hp1[0], hp1[1]);
            uint2 u1 = packpair(hp1[2], hp1[3]);
            *(uint2*)(g_h1hi[pw] + widxh) = make_uint2(u0.x, u1.x);
            *(uint2*)(g_h1lo[pw] + widxh) = make_uint2(u0.y, u1.y);
        }
        gsync(epoch);
    }

    // ---- epilogue: y(T-1); final h1 lives in buf 0 ----
    if (!is_main) {
        const uint32_t* hp = g_h1hi[0];
        const uint32_t* lp = g_h1lo[0];
        float acc[4] = {0.f, 0.f, 0.f, 0.f};
        uint4 vh, vl;
        stage_ld(vh, vl, hp, lp, oh0, oh1);
        stage_st(sm, 0, vh, vl);
#pragma unroll 1
        for (int c = 0; c < 8; c++) {
            __syncthreads();
            if (c < 7) stage_ld(vh, vl, hp, lp, oh0 + (c + 1) * 512,
                                oh1 + (c + 1) * 512);
            mma_chunk(acc, sm + ACT + (c & 1) * 2048, sm + 0, sm + 8192,
                      c * 4, rb, nb, lane);
            if (c < 7) stage_st(sm, (c + 1) & 1, vh, vl);
        }
        float b0v = miscf[ci], b1v = miscf[ci + 1];
        *(float2*)(out + g * (T * O) + (T - 1) * O + gc) =
            make_float2(acc[0] + b0v, acc[1] + b1v);
        *(float2*)(out + (g + 8) * (T * O) + (T - 1) * O + gc) =
            make_float2(acc[2] + b0v, acc[3] + b1v);
    }
}

extern "C" void kernel_launch(void* const* d_in, const int* in_sizes, int n_in,
                              void* d_out, int out_size) {
    const float* x    = (const float*)d_in[0];
    const float* Win0 = (const float*)d_in[1];
    const float* bin0 = (const float*)d_in[2];
    const float* A0   = (const float*)d_in[3];
    const float* tau0 = (const float*)d_in[4];
    const float* Win1 = (const float*)d_in[5];
    const float* bin1 = (const float*)d_in[6];
    const float* A1   = (const float*)d_in[7];
    const float* tau1 = (const float*)d_in[8];
    const float* Wout = (const float*)d_in[9];
    const float* bout = (const float*)d_in[10];
    float* out = (float*)d_out;

    cudaFuncSetAttribute(k_scan, cudaFuncAttributeMaxDynamicSharedMemorySize,
                         SMEM_BYTES);

    k_init<<<(HPLANE + 255) / 256, 256>>>();
    k_prep<<<512, 256>>>(x);
    k_scan<<<GRID, 256, SMEM_BYTES>>>(x, Win0, bin0, A0, tau0, Win1, bin1, A1,
                                      tau1, Wout, bout, out);
}

// round 9
// speedup vs baseline: 1.9859x; 1.2966x over previous
#include <cuda_runtime.h>
#include <cuda_bf16.h>
#include <math.h>
#include <stdint.h>

#define DT_STEP 0.1f
#define EPS_TAU 1e-6f

constexpr int B = 256, T = 512, I = 64, H = 512, O = 64;
constexpr int GRID = 144;   // 128 layer CTAs + 16 out-proj CTAs; all co-resident
constexpr int KP = H / 2;   // 256 kpairs per h row
constexpr int NKT = KP / 8; // 32 k16-tiles per h row

// smem b32 offsets
constexpr int WA_HI = 0;        // 9216 (K=576)
constexpr int WA_LO = 9216;
constexpr int WB_HI = 18432;    // 16384 (K=1024)
constexpr int WB_LO = 34816;
constexpr int ACT = 51200;      // 2 bufs x (1024 hi + 1024 lo)
constexpr int MISC = ACT + 4096;
constexpr int SMEM_BYTES = (MISC + 128) * 4;  // 221,696 B

// Global activation planes in MMA fragment order (see round 8 layout comment).
constexpr int HPLANE = (B / 16) * NKT * 128;    // 65536 u32
constexpr int XPLANE = (B / 16) * T * 4 * 128;

__device__ uint32_t g_h0hi[2][HPLANE], g_h0lo[2][HPLANE];
__device__ uint32_t g_h1hi[2][HPLANE], g_h1lo[2][HPLANE];
__device__ uint32_t g_pxhi[XPLANE], g_pxlo[XPLANE];
__device__ unsigned g_arrive;

__global__ void k_init() {
    int idx = blockIdx.x * blockDim.x + threadIdx.x;
    if (idx < HPLANE) {
        g_h0hi[0][idx] = 0u; g_h0hi[1][idx] = 0u;
        g_h0lo[0][idx] = 0u; g_h0lo[1][idx] = 0u;
        g_h1hi[0][idx] = 0u; g_h1hi[1][idx] = 0u;
        g_h1lo[0][idx] = 0u; g_h1lo[1][idx] = 0u;
    }
    if (idx == 0) g_arrive = 0;
}

__device__ __forceinline__ uint32_t pack2(float e0, float e1) {
    uint32_t r;  // low half = e0
    asm("cvt.rn.bf16x2.f32 %0, %1, %2;" : "=r"(r) : "f"(e1), "f"(e0));
    return r;
}
__device__ __forceinline__ float bfr(float x) {
    return __bfloat162float(__float2bfloat16_rn(x));
}
__device__ __forceinline__ uint2 packpair(float e0, float e1) {
    float h0 = bfr(e0), h1 = bfr(e1);
    return make_uint2(pack2(h0, h1), pack2(e0 - h0, e1 - h1));
}

// Pre-pack x into fragment-order planes (unchanged from round 8).
__global__ void k_prep(const float* __restrict__ x) {
    int n = (B / 16) * T * 4 * 32;
    for (int i = blockIdx.x * blockDim.x + threadIdx.x; i < n;
         i += gridDim.x * blockDim.x) {
        int lane = i & 31, ktx = (i >> 5) & 3, t = (i >> 7) & (T - 1), rbg = i >> 16;
        int gid = lane >> 2, tigf = lane & 3;
        int kp0 = ktx * 8 + tigf;
        const float* xb = x + (size_t)(rbg * 16 + gid) * (T * I) + t * I;
        const float* xb8 = xb + 8 * (T * I);
        float2 v0 = *(const float2*)(xb + kp0 * 2);
        float2 v1 = *(const float2*)(xb8 + kp0 * 2);
        float2 v2 = *(const float2*)(xb + (kp0 + 4) * 2);
        float2 v3 = *(const float2*)(xb8 + (kp0 + 4) * 2);
        uint2 p0 = packpair(v0.x, v0.y), p1 = packpair(v1.x, v1.y);
        uint2 p2 = packpair(v2.x, v2.y), p3 = packpair(v3.x, v3.y);
        *(uint4*)(g_pxhi + i * 4) = make_uint4(p0.x, p1.x, p2.x, p3.x);
        *(uint4*)(g_pxlo + i * 4) = make_uint4(p0.y, p1.y, p2.y, p3.y);
    }
}

__device__ __forceinline__ void mmaw(float* d, uint4 a, uint2 b) {
    asm volatile(
        "mma.sync.aligned.m16n8k16.row.col.f32.bf16.bf16.f32 "
        "{%0,%1,%2,%3},{%4,%5,%6,%7},{%8,%9},{%0,%1,%2,%3};"
        : "+f"(d[0]), "+f"(d[1]), "+f"(d[2]), "+f"(d[3])
        : "r"(a.x), "r"(a.y), "r"(a.z), "r"(a.w), "r"(b.x), "r"(b.y));
}

// Grid barrier: arrive on shared counter, everyone polls the counter itself
// (no release store hop). __threadfence() orders writes + invalidates L1D.
__device__ __forceinline__ void gsync(unsigned& epoch) {
    epoch++;
    __syncthreads();
    __threadfence();
    if (threadIdx.x == 0) {
        atomicAdd(&g_arrive, 1u);
        unsigned target = (unsigned)GRID * epoch;
        while (*(volatile unsigned*)&g_arrive < target) {}
    }
    __syncthreads();
    __threadfence();
}

// One-time weight staging into fragment order (unchanged).
__device__ void stage_wfrag(uint32_t* sm32, int hiOff, int loOff, int pairs,
                            const float* W0, int s0, int klim,
                            const float* W1, int s1) {
    for (int idx = threadIdx.x; idx < pairs; idx += 256) {
        int s = idx & 1, lane = (idx >> 1) & 31;
        int nb = (idx >> 6) & 3, ktG = idx >> 8;
        int gid = lane >> 2, tig = lane & 3;
        int n = nb * 8 + gid, k = ktG * 16 + tig * 2 + s * 8;
        const float* src; int kk;
        if (k < klim) { src = W0 + n * s0; kk = k; }
        else { src = W1 + n * s1; kk = k - klim; }
        float w0 = src[kk], w1 = src[kk + 1];
        float h0 = bfr(w0), h1 = bfr(w1);
        sm32[hiOff + idx] = pack2(h0, h1);
        sm32[loOff + idx] = pack2(w0 - h0, w1 - h1);
    }
}

__device__ __forceinline__ void stage_ld(uint4& vh, uint4& vl,
                                         const uint32_t* hp, const uint32_t* lp,
                                         int off0, int off1) {
    int tid = threadIdx.x;
    int off = ((tid >> 7) ? off1 : off0) + (tid & 127) * 4;
    vh = *(const uint4*)(hp + off);
    vl = *(const uint4*)(lp + off);
}
__device__ __forceinline__ void stage_st(uint32_t* sm, int bufIdx,
                                         uint4 vh, uint4 vl) {
    int tid = threadIdx.x;
    uint32_t* d = sm + ACT + bufIdx * 2048 + (tid >> 7) * 512 + (tid & 127) * 4;
    *(uint4*)d = vh;
    *(uint4*)(d + 1024) = vl;
}

// 4 k16-tiles of one staged chunk (A from smem, B frags resident, 3 HMMA each).
__device__ __forceinline__ void mma_chunk(float* acc, const uint32_t* smact,
                                          const uint32_t* whi, const uint32_t* wlo,
                                          int ktG0, int rb, int nb, int lane) {
#pragma unroll
    for (int ktl = 0; ktl < 4; ktl++) {
        const uint32_t* a = smact + (rb * 4 + ktl) * 128 + lane * 4;
        uint4 ah = *(const uint4*)a;
        uint4 al = *(const uint4*)(a + 1024);
        int widx = (ktG0 + ktl) * 4 + nb;
        uint2 bh = *(const uint2*)(whi + (widx * 32 + lane) * 2);
        uint2 bl = *(const uint2*)(wlo + (widx * 32 + lane) * 2);
        mmaw(acc, ah, bh);
        mmaw(acc, ah, bl);
        mmaw(acc, al, bh);
    }
}

// Merged-interval persistent scan: interval t computes A(t) [h0(t)] AND
// B(t-1) [h1(t-1)] sharing the staged h0(t-1) chunks; out-CTAs emit y(t-2).
// ONE grid barrier per interval; T+2 intervals.
__global__ __launch_bounds__(256, 1) void k_scan(
    const float* __restrict__ x, const float* __restrict__ Win0,
    const float* __restrict__ bin0, const float* __restrict__ A0,
    const float* __restrict__ tau0, const float* __restrict__ Win1,
    const float* __restrict__ bin1, const float* __restrict__ A1,
    const float* __restrict__ tau1, const float* __restrict__ Wout,
    const float* __restrict__ bout, float* __restrict__ out) {
    extern __shared__ uint32_t sm[];
    float* miscf = (float*)(sm + MISC);
    const int tid = threadIdx.x, bx = blockIdx.x;
    const int w = tid >> 5, lane = tid & 31;
    const int gid = lane >> 2, tig = lane & 3;
    const int rb = w & 1, nb = w >> 1;
    const bool is_main = (bx < 128);
    int row0, col0;
    if (is_main) { row0 = (bx >> 4) * 32; col0 = (bx & 15) * 32; }
    else { int idx = bx - 128; row0 = (idx >> 1) * 32; col0 = (idx & 1) * 32; }

    if (is_main) {
        stage_wfrag(sm, WA_HI, WA_LO, 9216, A0 + col0 * H, H, 512,
                    Win0 + col0 * I, I);
        stage_wfrag(sm, WB_HI, WB_LO, 16384, Win1 + col0 * H, H, 512,
                    A1 + col0 * H, H);
        if (tid < 32) {
            miscf[tid] = bin0[col0 + tid];
            miscf[32 + tid] = 1.0f / (fabsf(tau0[col0 + tid]) + EPS_TAU);
            miscf[64 + tid] = bin1[col0 + tid];
            miscf[96 + tid] = 1.0f / (fabsf(tau1[col0 + tid]) + EPS_TAU);
        }
    } else {
        stage_wfrag(sm, 0, 8192, 8192, Wout + col0 * H, H, 1 << 20, Wout, H);
        if (tid < 32) miscf[tid] = bout[col0 + tid];
    }
    __syncthreads();

    const int g = row0 + rb * 16 + gid;
    const int gc = col0 + nb * 8 + tig * 2;
    const int ci = nb * 8 + tig * 2;
    const int kpw = gc >> 1;
    const int rbg0 = row0 >> 4;
    const int wrbg = rbg0 + rb;
    const int widxh = ((wrbg * NKT + (kpw >> 3)) * 32 + gid * 4 + (kpw & 3)) * 4 +
                      ((kpw >> 2) & 1) * 2;
    const int oh0 = rbg0 * NKT * 128, oh1 = (rbg0 + 1) * NKT * 128;

    float hp0[4] = {0.f, 0.f, 0.f, 0.f};
    float hp1[4] = {0.f, 0.f, 0.f, 0.f};
    unsigned epoch = 0;

    for (int t = 0; t < T + 2; t++) {
        const int prh0 = (t - 1) & 1;  // h0(t-1)
        const int pwh0 = t & 1;        // h0(t)
        const int prh1 = t & 1;        // h1(t-2) parity == t&1
        const int pwh1 = (t - 1) & 1;  // h1(t-1)
        const bool doA = (t < T), doB = (t >= 1 && t <= T);

        if (is_main) {
            if (doA || doB) {
                const uint32_t* h0h = g_h0hi[prh0];
                const uint32_t* h0l = g_h0lo[prh0];
                const uint32_t* h1h = g_h1hi[prh1];
                const uint32_t* h1l = g_h1lo[prh1];
                const int tx = doA ? t : 0;  // dummy (unused) x when !doA
                const int ox0 = (rbg0 * T + tx) * 512, ox1 = ((rbg0 + 1) * T + tx) * 512;
                float accA[4] = {0.f, 0.f, 0.f, 0.f};
                float accB[4] = {0.f, 0.f, 0.f, 0.f};
                uint4 vh, vl;
                stage_ld(vh, vl, h0h, h0l, oh0, oh1);
                stage_st(sm, 0, vh, vl);
#pragma unroll 1
                for (int c = 0; c < 17; c++) {
                    __syncthreads();
                    if (c < 16) {
                        int cn = c + 1;
                        if (cn < 8)
                            stage_ld(vh, vl, h0h, h0l, oh0 + cn * 512, oh1 + cn * 512);
                        else if (cn == 8)
                            stage_ld(vh, vl, g_pxhi, g_pxlo, ox0, ox1);
                        else
                            stage_ld(vh, vl, h1h, h1l, oh0 + (cn - 9) * 512,
                                     oh1 + (cn - 9) * 512);
                    }
                    const uint32_t* ab = sm + ACT + (c & 1) * 2048;
                    if (c < 8) {
                        if (doA) mma_chunk(accA, ab, sm + WA_HI, sm + WA_LO, c * 4,
                                           rb, nb, lane);
                        if (doB) mma_chunk(accB, ab, sm + WB_HI, sm + WB_LO, c * 4,
                                           rb, nb, lane);
                    } else if (c == 8) {
                        if (doA) mma_chunk(accA, ab, sm + WA_HI, sm + WA_LO, 32,
                                           rb, nb, lane);
                    } else {
                        if (doB) mma_chunk(accB, ab, sm + WB_HI, sm + WB_LO,
                                           32 + (c - 9) * 4, rb, nb, lane);
                    }
                    if (c < 16) stage_st(sm, (c + 1) & 1, vh, vl);
                    if (c == 8 && doA) {
                        // early epilogue A: finish h0(t), overlap stores with B chunks
                        float b0v = miscf[ci], b1v = miscf[ci + 1];
                        float i0 = miscf[32 + ci], i1 = miscf[32 + ci + 1];
                        hp0[0] += DT_STEP * i0 * (tanhf(accA[0] + b0v) - hp0[0]);
                        hp0[1] += DT_STEP * i1 * (tanhf(accA[1] + b1v) - hp0[1]);
                        hp0[2] += DT_STEP * i0 * (tanhf(accA[2] + b0v) - hp0[2]);
                        hp0[3] += DT_STEP * i1 * (tanhf(accA[3] + b1v) - hp0[3]);
                        uint2 u0 = packpair(hp0[0], hp0[1]);
                        uint2 u1 = packpair(hp0[2], hp0[3]);
                        *(uint2*)(g_h0hi[pwh0] + widxh) = make_uint2(u0.x, u1.x);
                        *(uint2*)(g_h0lo[pwh0] + widxh) = make_uint2(u0.y, u1.y);
                    }
                }
                if (doB) {
                    float b0v = miscf[64 + ci], b1v = miscf[64 + ci + 1];
                    float i0 = miscf[96 + ci], i1 = miscf[96 + ci + 1];
                    hp1[0] += DT_STEP * i0 * (tanhf(accB[0] + b0v) - hp1[0]);
                    hp1[1] += DT_STEP * i1 * (tanhf(accB[1] + b1v) - hp1[1]);
                    hp1[2] += DT_STEP * i0 * (tanhf(accB[2] + b0v) - hp1[2]);
                    hp1[3] += DT_STEP * i1 * (tanhf(accB[3] + b1v) - hp1[3]);
                    uint2 u0 = packpair(hp1[0], hp1[1]);
                    uint2 u1 = packpair(hp1[2], hp1[3]);
                    *(uint2*)(g_h1hi[pwh1] + widxh) = make_uint2(u0.x, u1.x);
                    *(uint2*)(g_h1lo[pwh1] + widxh) = make_uint2(u0.y, u1.y);
                }
            }
        } else if (t >= 2) {
            // y(t-2) = h1(t-2) @ Wout^T + bout; h1(t-2) parity == t&1
            const uint32_t* hp = g_h1hi[t & 1];
            const uint32_t* lp = g_h1lo[t & 1];
            float acc[4] = {0.f, 0.f, 0.f, 0.f};
            uint4 vh, vl;
            stage_ld(vh, vl, hp, lp, oh0, oh1);
            stage_st(sm, 0, vh, vl);
#pragma unroll 1
            for (int c = 0; c < 8; c++) {
                __syncthreads();
                if (c < 7) stage_ld(vh, vl, hp, lp, oh0 + (c + 1) * 512,
                                    oh1 + (c + 1) * 512);
                mma_chunk(acc, sm + ACT + (c & 1) * 2048, sm + 0, sm + 8192,
                          c * 4, rb, nb, lane);
                if (c < 7) stage_st(sm, (c + 1) & 1, vh, vl);
            }
            float b0v = miscf[ci], b1v = miscf[ci + 1];
            *(float2*)(out + g * (T * O) + (t - 2) * O + gc) =
                make_float2(acc[0] + b0v, acc[1] + b1v);
            *(float2*)(out + (g + 8) * (T * O) + (t - 2) * O + gc) =
                make_float2(acc[2] + b0v, acc[3] + b1v);
        }
        gsync(epoch);
    }
}

extern "C" void kernel_launch(void* const* d_in, const int* in_sizes, int n_in,
                              void* d_out, int out_size) {
    const float* x    = (const float*)d_in[0];
    const float* Win0 = (const float*)d_in[1];
    const float* bin0 = (const float*)d_in[2];
    const float* A0   = (const float*)d_in[3];
    const float* tau0 = (const float*)d_in[4];
    const float* Win1 = (const float*)d_in[5];
    const float* bin1 = (const float*)d_in[6];
    const float* A1   = (const float*)d_in[7];
    const float* tau1 = (const float*)d_in[8];
    const float* Wout = (const float*)d_in[9];
    const float* bout = (const float*)d_in[10];
    float* out = (float*)d_out;

    cudaFuncSetAttribute(k_scan, cudaFuncAttributeMaxDynamicSharedMemorySize,
                         SMEM_BYTES);

    k_init<<<(HPLANE + 255) / 256, 256>>>();
    k_prep<<<512, 256>>>(x);
    k_scan<<<GRID, 256, SMEM_BYTES>>>(x, Win0, bin0, A0, tau0, Win1, bin1, A1,
                                      tau1, Wout, bout, out);
}